// round 1
// baseline (speedup 1.0000x reference)
#include <cuda_runtime.h>
#include <math.h>

#define T_TOK 2048
#define H_DIM 1024
#define E_NUM 8
#define I_DIM 2048

// ---------------- device scratch (static: no allocations allowed) ----------------
__device__ int   g_count[E_NUM];
__device__ int   g_tok[E_NUM][T_TOK];
__device__ float g_wt[E_NUM][T_TOK];
// act[e][pos][i] : 8 * 2048 * 2048 floats = 128 MB
__device__ float g_act[(size_t)E_NUM * T_TOK * I_DIM];

// ---------------- kernel 0: zero per-expert counters ----------------
__global__ void zero_counts_kernel() {
    if (threadIdx.x < E_NUM) g_count[threadIdx.x] = 0;
}

// ---------------- kernel 1: router ----------------
// One block (128 threads) per token. logits = x @ gate_w  (gate_w is [H, E] row-major).
// softcap: tanh(logit/30); top-2 with lax.top_k tie semantics; softmax over the 2.
__global__ void router_kernel(const float* __restrict__ hs, const float* __restrict__ gw) {
    int t = blockIdx.x;
    const float* x = hs + (size_t)t * H_DIM;
    float acc[E_NUM];
#pragma unroll
    for (int e = 0; e < E_NUM; e++) acc[e] = 0.f;
    for (int j = threadIdx.x; j < H_DIM; j += blockDim.x) {
        float xv = x[j];
        const float4* grow = reinterpret_cast<const float4*>(gw + (size_t)j * E_NUM);
        float4 g0 = grow[0], g1 = grow[1];
        acc[0] += xv * g0.x; acc[1] += xv * g0.y; acc[2] += xv * g0.z; acc[3] += xv * g0.w;
        acc[4] += xv * g1.x; acc[5] += xv * g1.y; acc[6] += xv * g1.z; acc[7] += xv * g1.w;
    }
#pragma unroll
    for (int off = 16; off > 0; off >>= 1) {
#pragma unroll
        for (int e = 0; e < E_NUM; e++)
            acc[e] += __shfl_xor_sync(0xffffffffu, acc[e], off);
    }
    __shared__ float s[4][E_NUM];
    int warp = threadIdx.x >> 5, lane = threadIdx.x & 31;
    if (lane == 0) {
#pragma unroll
        for (int e = 0; e < E_NUM; e++) s[warp][e] = acc[e];
    }
    __syncthreads();
    if (threadIdx.x == 0) {
        float l[E_NUM];
#pragma unroll
        for (int e = 0; e < E_NUM; e++)
            l[e] = tanhf((s[0][e] + s[1][e] + s[2][e] + s[3][e]) * (1.0f / 30.0f));
        int i0 = 0;
#pragma unroll
        for (int e = 1; e < E_NUM; e++) if (l[e] > l[i0]) i0 = e;
        int i1 = (i0 == 0) ? 1 : 0;
#pragma unroll
        for (int e = 0; e < E_NUM; e++) if (e != i0 && l[e] > l[i1]) i1 = e;
        float d  = l[i1] - l[i0];              // <= 0
        float ed = expf(d);
        float inv = 1.0f / (1.0f + ed);
        float p0 = inv;
        float p1 = ed * inv;
        int p = atomicAdd(&g_count[i0], 1);
        g_tok[i0][p] = t; g_wt[i0][p] = p0;
        p = atomicAdd(&g_count[i1], 1);
        g_tok[i1][p] = t; g_wt[i1][p] = p1;
    }
}

// tanh-approx GELU (jax.nn.gelu default: approximate=True)
__device__ __forceinline__ float gelu_tanh(float g) {
    float c = 0.7978845608028654f * (g + 0.044715f * g * g * g);
    return 0.5f * g * (1.0f + tanhf(c));
}

// ---------------- kernel 2: grouped up-proj  act = gelu(X@wg) * (X@wu) ----------------
// Block tile: 128 (gathered rows) x 64 (I cols) for BOTH g and u (shared A tile).
// 256 threads: tx in [0,16) (4 N cols), ty in [0,16) (8 M rows: ty*4..+3 and 64+ty*4..+3).
__global__ __launch_bounds__(256)
void expert_gu_kernel(const float* __restrict__ hs,
                      const float* __restrict__ wg,
                      const float* __restrict__ wu) {
    const int e = blockIdx.z;
    const int count = g_count[e];
    const int m0 = blockIdx.y * 128;
    if (m0 >= count) return;
    const int n0 = blockIdx.x * 64;

    __shared__ float As[16][128];
    __shared__ float Bg[16][64];
    __shared__ float Bu[16][64];
    __shared__ int   rowtok[128];

    const int tid = threadIdx.x;
    if (tid < 128) {
        int gpos = m0 + tid;
        rowtok[tid] = (gpos < count) ? g_tok[e][gpos] : -1;
    }
    __syncthreads();

    const float* wgp = wg + (size_t)e * H_DIM * I_DIM;
    const float* wup = wu + (size_t)e * H_DIM * I_DIM;

    float accg[8][4], accu[8][4];
#pragma unroll
    for (int i = 0; i < 8; i++)
#pragma unroll
        for (int j = 0; j < 4; j++) { accg[i][j] = 0.f; accu[i][j] = 0.f; }

    const int tx = tid & 15, ty = tid >> 4;

    for (int k0 = 0; k0 < H_DIM; k0 += 16) {
        // A: 128 rows x 16 k, gathered; 2 float4 per thread, stored transposed As[k][m]
#pragma unroll
        for (int it = 0; it < 2; it++) {
            int f  = tid + it * 256;
            int r  = f >> 2;
            int cg = (f & 3) * 4;
            int tok = rowtok[r];
            float4 v = make_float4(0.f, 0.f, 0.f, 0.f);
            if (tok >= 0)
                v = *reinterpret_cast<const float4*>(hs + (size_t)tok * H_DIM + k0 + cg);
            As[cg + 0][r] = v.x; As[cg + 1][r] = v.y; As[cg + 2][r] = v.z; As[cg + 3][r] = v.w;
        }
        // B tiles: 16 x 64 each, 1 float4 per thread, natural layout
        {
            int f = tid;
            int r = f >> 4;
            int c = f & 15;
            reinterpret_cast<float4*>(&Bg[r][0])[c] =
                *reinterpret_cast<const float4*>(wgp + (size_t)(k0 + r) * I_DIM + n0 + c * 4);
            reinterpret_cast<float4*>(&Bu[r][0])[c] =
                *reinterpret_cast<const float4*>(wup + (size_t)(k0 + r) * I_DIM + n0 + c * 4);
        }
        __syncthreads();
#pragma unroll
        for (int kk = 0; kk < 16; kk++) {
            float4 a0 = *reinterpret_cast<const float4*>(&As[kk][ty * 4]);
            float4 a1 = *reinterpret_cast<const float4*>(&As[kk][64 + ty * 4]);
            float4 bg = *reinterpret_cast<const float4*>(&Bg[kk][tx * 4]);
            float4 bu = *reinterpret_cast<const float4*>(&Bu[kk][tx * 4]);
            float a[8]  = {a0.x, a0.y, a0.z, a0.w, a1.x, a1.y, a1.z, a1.w};
            float bgv[4] = {bg.x, bg.y, bg.z, bg.w};
            float buv[4] = {bu.x, bu.y, bu.z, bu.w};
#pragma unroll
            for (int i = 0; i < 8; i++)
#pragma unroll
                for (int j = 0; j < 4; j++) {
                    accg[i][j] += a[i] * bgv[j];
                    accu[i][j] += a[i] * buv[j];
                }
        }
        __syncthreads();
    }

#pragma unroll
    for (int i = 0; i < 8; i++) {
        int rl = (i < 4) ? (ty * 4 + i) : (64 + ty * 4 + (i - 4));
        int gpos = m0 + rl;
        if (gpos < count) {
            float4 o;
            float g0 = accg[i][0], g1 = accg[i][1], g2 = accg[i][2], g3 = accg[i][3];
            o.x = gelu_tanh(g0) * accu[i][0];
            o.y = gelu_tanh(g1) * accu[i][1];
            o.z = gelu_tanh(g2) * accu[i][2];
            o.w = gelu_tanh(g3) * accu[i][3];
            *reinterpret_cast<float4*>(
                &g_act[((size_t)e * T_TOK + gpos) * I_DIM + n0 + tx * 4]) = o;
        }
    }
}

// ---------------- kernel 3: grouped down-proj + weighted combine ----------------
// y = act @ wd  (K=2048, N=1024). Block tile 128x128, thread 8x8.
// Epilogue: atomicAdd(out[tok, n], weight * y) — each out element receives exactly 2
// fp32 adds onto 0 (commutative -> deterministic).
__global__ __launch_bounds__(256)
void expert_down_kernel(const float* __restrict__ wd, float* __restrict__ out) {
    const int e = blockIdx.z;
    const int count = g_count[e];
    const int m0 = blockIdx.y * 128;
    if (m0 >= count) return;
    const int n0 = blockIdx.x * 128;

    __shared__ float As[16][128];
    __shared__ float Bs[16][128];

    const int tid = threadIdx.x;
    const int tx = tid & 15, ty = tid >> 4;
    const float* wdp  = wd + (size_t)e * I_DIM * H_DIM;
    const float* actp = g_act + (size_t)e * T_TOK * I_DIM;

    float acc[8][8];
#pragma unroll
    for (int i = 0; i < 8; i++)
#pragma unroll
        for (int j = 0; j < 8; j++) acc[i][j] = 0.f;

    for (int k0 = 0; k0 < I_DIM; k0 += 16) {
        // A: act rows (contiguous, no gather), transposed store
#pragma unroll
        for (int it = 0; it < 2; it++) {
            int f  = tid + it * 256;
            int r  = f >> 2;
            int cg = (f & 3) * 4;
            int gpos = m0 + r;
            float4 v = make_float4(0.f, 0.f, 0.f, 0.f);
            if (gpos < count)
                v = *reinterpret_cast<const float4*>(actp + (size_t)gpos * I_DIM + k0 + cg);
            As[cg + 0][r] = v.x; As[cg + 1][r] = v.y; As[cg + 2][r] = v.z; As[cg + 3][r] = v.w;
        }
        // B: wd tile 16 x 128, natural layout, 2 float4 per thread
#pragma unroll
        for (int it = 0; it < 2; it++) {
            int f = tid + it * 256;
            int r = f >> 5;
            int c = f & 31;
            reinterpret_cast<float4*>(&Bs[r][0])[c] =
                *reinterpret_cast<const float4*>(wdp + (size_t)(k0 + r) * H_DIM + n0 + c * 4);
        }
        __syncthreads();
#pragma unroll
        for (int kk = 0; kk < 16; kk++) {
            float4 a0 = *reinterpret_cast<const float4*>(&As[kk][ty * 4]);
            float4 a1 = *reinterpret_cast<const float4*>(&As[kk][64 + ty * 4]);
            float4 b0 = *reinterpret_cast<const float4*>(&Bs[kk][tx * 4]);
            float4 b1 = *reinterpret_cast<const float4*>(&Bs[kk][64 + tx * 4]);
            float a[8] = {a0.x, a0.y, a0.z, a0.w, a1.x, a1.y, a1.z, a1.w};
            float b[8] = {b0.x, b0.y, b0.z, b0.w, b1.x, b1.y, b1.z, b1.w};
#pragma unroll
            for (int i = 0; i < 8; i++)
#pragma unroll
                for (int j = 0; j < 8; j++)
                    acc[i][j] += a[i] * b[j];
        }
        __syncthreads();
    }

#pragma unroll
    for (int i = 0; i < 8; i++) {
        int rl = (i < 4) ? (ty * 4 + i) : (64 + ty * 4 + (i - 4));
        int gpos = m0 + rl;
        if (gpos >= count) continue;
        int tok  = g_tok[e][gpos];
        float w  = g_wt[e][gpos];
        float* orow = out + (size_t)tok * H_DIM + n0;
#pragma unroll
        for (int j = 0; j < 8; j++) {
            int cl = (j < 4) ? (tx * 4 + j) : (64 + tx * 4 + (j - 4));
            atomicAdd(&orow[cl], w * acc[i][j]);
        }
    }
}

// ---------------- launch ----------------
extern "C" void kernel_launch(void* const* d_in, const int* in_sizes, int n_in,
                              void* d_out, int out_size) {
    const float* hs = (const float*)d_in[0];   // [T, H]
    const float* gw = (const float*)d_in[1];   // [H, E]
    const float* wg = (const float*)d_in[2];   // [E, H, I]
    const float* wu = (const float*)d_in[3];   // [E, H, I]
    const float* wd = (const float*)d_in[4];   // [E, I, H]
    float* out = (float*)d_out;                // [T, H]

    cudaMemsetAsync(d_out, 0, (size_t)T_TOK * H_DIM * sizeof(float));
    zero_counts_kernel<<<1, 32>>>();
    router_kernel<<<T_TOK, 128>>>(hs, gw);

    dim3 gridA(I_DIM / 64, T_TOK / 128, E_NUM);
    expert_gu_kernel<<<gridA, 256>>>(hs, wg, wu);

    dim3 gridB(H_DIM / 128, T_TOK / 128, E_NUM);
    expert_down_kernel<<<gridB, 256>>>(wd, out);
}

// round 3
// speedup vs baseline: 1.0948x; 1.0948x over previous
#include <cuda_runtime.h>
#include <math.h>
#include <stdint.h>

#define T_TOK 2048
#define H_DIM 1024
#define E_NUM 8
#define I_DIM 2048

// ---------------- device scratch ----------------
__device__ int   g_count[E_NUM];
__device__ int   g_tok[E_NUM][T_TOK];
__device__ float g_wt[E_NUM][T_TOK];
__device__ int   g_slot[T_TOK][2];
__device__ float g_act[(size_t)E_NUM * T_TOK * I_DIM];   // 128 MB (tf32-rounded values)
__device__ float g_y[(size_t)E_NUM * T_TOK * H_DIM];     // 64 MB

// ---------------- helpers ----------------
__device__ __forceinline__ uint32_t to_tf32(float x) {
    uint32_t r; asm("cvt.rna.tf32.f32 %0, %1;" : "=r"(r) : "f"(x)); return r;
}
__device__ __forceinline__ float to_tf32f(float x) {
    return __uint_as_float(to_tf32(x));
}
__device__ __forceinline__ void mma_tf32(float* c, const uint32_t* a, const uint32_t* b) {
    asm volatile(
        "mma.sync.aligned.m16n8k8.row.col.f32.tf32.tf32.f32 "
        "{%0,%1,%2,%3}, {%4,%5,%6,%7}, {%8,%9}, {%0,%1,%2,%3};"
        : "+f"(c[0]), "+f"(c[1]), "+f"(c[2]), "+f"(c[3])
        : "r"(a[0]), "r"(a[1]), "r"(a[2]), "r"(a[3]), "r"(b[0]), "r"(b[1]));
}

// ---------------- small kernels ----------------
__global__ void zero_counts_kernel() {
    if (threadIdx.x < E_NUM) g_count[threadIdx.x] = 0;
}

__global__ void router_kernel(const float* __restrict__ hs, const float* __restrict__ gw) {
    int t = blockIdx.x;
    const float* x = hs + (size_t)t * H_DIM;
    float acc[E_NUM];
#pragma unroll
    for (int e = 0; e < E_NUM; e++) acc[e] = 0.f;
    for (int j = threadIdx.x; j < H_DIM; j += blockDim.x) {
        float xv = x[j];
        const float4* grow = reinterpret_cast<const float4*>(gw + (size_t)j * E_NUM);
        float4 g0 = grow[0], g1 = grow[1];
        acc[0] += xv * g0.x; acc[1] += xv * g0.y; acc[2] += xv * g0.z; acc[3] += xv * g0.w;
        acc[4] += xv * g1.x; acc[5] += xv * g1.y; acc[6] += xv * g1.z; acc[7] += xv * g1.w;
    }
#pragma unroll
    for (int off = 16; off > 0; off >>= 1)
#pragma unroll
        for (int e = 0; e < E_NUM; e++)
            acc[e] += __shfl_xor_sync(0xffffffffu, acc[e], off);
    __shared__ float s[4][E_NUM];
    int warp = threadIdx.x >> 5, lane = threadIdx.x & 31;
    if (lane == 0)
#pragma unroll
        for (int e = 0; e < E_NUM; e++) s[warp][e] = acc[e];
    __syncthreads();
    if (threadIdx.x == 0) {
        float l[E_NUM];
#pragma unroll
        for (int e = 0; e < E_NUM; e++)
            l[e] = tanhf((s[0][e] + s[1][e] + s[2][e] + s[3][e]) * (1.0f / 30.0f));
        int i0 = 0;
#pragma unroll
        for (int e = 1; e < E_NUM; e++) if (l[e] > l[i0]) i0 = e;
        int i1 = (i0 == 0) ? 1 : 0;
#pragma unroll
        for (int e = 0; e < E_NUM; e++) if (e != i0 && l[e] > l[i1]) i1 = e;
        float d  = l[i1] - l[i0];
        float ed = expf(d);
        float inv = 1.0f / (1.0f + ed);
        float p0 = inv, p1 = ed * inv;
        int p = atomicAdd(&g_count[i0], 1);
        g_tok[i0][p] = t; g_wt[i0][p] = p0; g_slot[t][0] = i0 * T_TOK + p;
        p = atomicAdd(&g_count[i1], 1);
        g_tok[i1][p] = t; g_wt[i1][p] = p1; g_slot[t][1] = i1 * T_TOK + p;
    }
}

__device__ __forceinline__ float gelu_tanh(float g) {
    float c = 0.7978845608028654f * (g + 0.044715f * g * g * g);
    return 0.5f * g * (1.0f + tanhf(c));
}

// ============================================================================
// GEMM1: act = tf32( gelu(X@wg) * (X@wu) )   [per expert, gathered rows]
// CTA tile: M=128 x N=64 (both g and u). K=1024, kb=32, double-buffered.
// SMEM per stage (floats): A-frags 4096, Bg-frags 2048, Bu-frags 2048 = 8192.
// Frag layouts: A slot ((ks*8+mt)*32+lane)*4+reg ; B slot ((ks*8+nt)*32+lane)*2+reg
// ============================================================================
__global__ __launch_bounds__(256, 1)
void gemm1_kernel(const float* __restrict__ hs,
                  const float* __restrict__ wg,
                  const float* __restrict__ wu) {
    const int e = blockIdx.z;
    const int count = g_count[e];
    const int m0 = blockIdx.y * 128;
    if (m0 >= count) return;
    const int n0 = blockIdx.x * 64;

    extern __shared__ float sm[];
    __shared__ int rowtok[128];

    const int tid = threadIdx.x, wid = tid >> 5, lane = tid & 31;
    const int wm = wid & 1, wn = wid >> 1;

    if (tid < 128) {
        int gp = m0 + tid;
        rowtok[tid] = (gp < count) ? g_tok[e][gp] : -1;
    }
    __syncthreads();

    const float* wgp = wg + (size_t)e * H_DIM * I_DIM + n0;
    const float* wup = wu + (size_t)e * H_DIM * I_DIM + n0;

    float accg[4][2][4], accu[4][2][4];
#pragma unroll
    for (int i = 0; i < 4; i++)
#pragma unroll
        for (int j = 0; j < 2; j++)
#pragma unroll
            for (int q = 0; q < 4; q++) { accg[i][j][q] = 0.f; accu[i][j][q] = 0.f; }

    float4 rA[4], rBg[2], rBu[2];

    // ---- loaders ----
#define G1_LOAD(k0)                                                                   \
    {                                                                                 \
        _Pragma("unroll")                                                             \
        for (int it = 0; it < 4; ++it) {                                              \
            int f = tid + it * 256;                                                   \
            int m = f >> 3, kq = (f & 7) << 2;                                        \
            int tok = rowtok[m];                                                      \
            rA[it] = (tok >= 0)                                                       \
                ? *reinterpret_cast<const float4*>(hs + (size_t)tok * H_DIM + (k0) + kq) \
                : make_float4(0.f, 0.f, 0.f, 0.f);                                    \
        }                                                                             \
        _Pragma("unroll")                                                             \
        for (int it = 0; it < 2; ++it) {                                              \
            int f = tid + it * 256;                                                   \
            int k = f >> 4, nq = (f & 15) << 2;                                       \
            rBg[it] = *reinterpret_cast<const float4*>(wgp + (size_t)((k0) + k) * I_DIM + nq); \
            rBu[it] = *reinterpret_cast<const float4*>(wup + (size_t)((k0) + k) * I_DIM + nq); \
        }                                                                             \
    }

#define G1_STORE(s)                                                                   \
    {                                                                                 \
        float* As = sm + (s) * 8192;                                                  \
        float* Bgs = As + 4096;                                                       \
        float* Bus = As + 6144;                                                       \
        _Pragma("unroll")                                                             \
        for (int it = 0; it < 4; ++it) {                                              \
            int f = tid + it * 256;                                                   \
            int m = f >> 3, kq = (f & 7) << 2;                                        \
            int ks = kq >> 3, chalf = (kq >> 2) & 1;                                  \
            int reg = ((m >> 3) & 1) + 2 * chalf;                                     \
            int mt = m >> 4, lane0 = (m & 7) << 2;                                    \
            int idx = ((ks * 8 + mt) * 32 + lane0) * 4 + reg;                         \
            As[idx + 0]  = to_tf32f(rA[it].x);                                        \
            As[idx + 4]  = to_tf32f(rA[it].y);                                        \
            As[idx + 8]  = to_tf32f(rA[it].z);                                        \
            As[idx + 12] = to_tf32f(rA[it].w);                                        \
        }                                                                             \
        _Pragma("unroll")                                                             \
        for (int it = 0; it < 2; ++it) {                                              \
            int f = tid + it * 256;                                                   \
            int k = f >> 4, nq = (f & 15) << 2;                                       \
            int ks = k >> 3, reg = (k >> 2) & 1, lk = k & 3;                          \
            float vg[4] = {rBg[it].x, rBg[it].y, rBg[it].z, rBg[it].w};               \
            float vu[4] = {rBu[it].x, rBu[it].y, rBu[it].z, rBu[it].w};               \
            _Pragma("unroll")                                                         \
            for (int i = 0; i < 4; ++i) {                                             \
                int n = nq + i;                                                       \
                int nt = n >> 3;                                                      \
                int ln = lk + ((n & 7) << 2);                                         \
                int idx = ((ks * 8 + nt) * 32 + ln) * 2 + reg;                        \
                Bgs[idx] = to_tf32f(vg[i]);                                           \
                Bus[idx] = to_tf32f(vu[i]);                                           \
            }                                                                         \
        }                                                                             \
    }

#define G1_MMA(s)                                                                     \
    {                                                                                 \
        const float* As = sm + (s) * 8192;                                            \
        const float* Bgs = As + 4096;                                                 \
        const float* Bus = As + 6144;                                                 \
        _Pragma("unroll")                                                             \
        for (int ks = 0; ks < 4; ++ks) {                                              \
            uint4 af[4];                                                              \
            _Pragma("unroll")                                                         \
            for (int mt = 0; mt < 4; ++mt)                                            \
                af[mt] = *reinterpret_cast<const uint4*>(                             \
                    As + ((ks * 8 + wm * 4 + mt) * 32 + lane) * 4);                   \
            uint2 bgf[2], buf_[2];                                                    \
            _Pragma("unroll")                                                         \
            for (int nt = 0; nt < 2; ++nt) {                                          \
                bgf[nt] = *reinterpret_cast<const uint2*>(                            \
                    Bgs + ((ks * 8 + wn * 2 + nt) * 32 + lane) * 2);                  \
                buf_[nt] = *reinterpret_cast<const uint2*>(                           \
                    Bus + ((ks * 8 + wn * 2 + nt) * 32 + lane) * 2);                  \
            }                                                                         \
            _Pragma("unroll")                                                         \
            for (int mt = 0; mt < 4; ++mt)                                            \
                _Pragma("unroll")                                                     \
                for (int nt = 0; nt < 2; ++nt) {                                      \
                    mma_tf32(accg[mt][nt], (const uint32_t*)&af[mt], (const uint32_t*)&bgf[nt]); \
                    mma_tf32(accu[mt][nt], (const uint32_t*)&af[mt], (const uint32_t*)&buf_[nt]); \
                }                                                                     \
        }                                                                             \
    }

    G1_LOAD(0);
    G1_STORE(0);
    __syncthreads();

    const int NC = H_DIM / 32;
    for (int c = 0; c < NC; ++c) {
        if (c + 1 < NC) G1_LOAD((c + 1) * 32);
        G1_MMA(c & 1);
        __syncthreads();
        if (c + 1 < NC) {
            G1_STORE((c + 1) & 1);
            __syncthreads();
        }
    }

    // ---- epilogue: fused gelu(g)*u, pre-rounded to tf32 for GEMM2 ----
#pragma unroll
    for (int mt = 0; mt < 4; ++mt) {
        int row_base = wm * 64 + mt * 16 + (lane >> 2);
#pragma unroll
        for (int nt = 0; nt < 2; ++nt) {
            int col = wn * 16 + nt * 8 + (lane & 3) * 2;
#pragma unroll
            for (int h = 0; h < 2; ++h) {
                int gpos = m0 + row_base + h * 8;
                if (gpos < count) {
                    float gv0 = accg[mt][nt][2 * h], gv1 = accg[mt][nt][2 * h + 1];
                    float uv0 = accu[mt][nt][2 * h], uv1 = accu[mt][nt][2 * h + 1];
                    float2 o;
                    o.x = to_tf32f(gelu_tanh(gv0) * uv0);
                    o.y = to_tf32f(gelu_tanh(gv1) * uv1);
                    *reinterpret_cast<float2*>(
                        g_act + ((size_t)e * T_TOK + gpos) * I_DIM + n0 + col) = o;
                }
            }
        }
    }
#undef G1_LOAD
#undef G1_STORE
#undef G1_MMA
}

// ============================================================================
// GEMM2: y = weight * (act @ wd)   [per expert]
// CTA tile: M=128 x N=128. K=2048, kb=32, double-buffered.
// SMEM per stage (floats): A-frags 4096, B-frags 4096 = 8192.
// ============================================================================
__global__ __launch_bounds__(256, 1)
void gemm2_kernel(const float* __restrict__ wd) {
    const int e = blockIdx.z;
    const int count = g_count[e];
    const int m0 = blockIdx.y * 128;
    if (m0 >= count) return;
    const int n0 = blockIdx.x * 128;

    extern __shared__ float sm[];

    const int tid = threadIdx.x, wid = tid >> 5, lane = tid & 31;
    const int wm = wid & 1, wn = wid >> 1;

    const float* actp = g_act + (size_t)e * T_TOK * I_DIM;
    const float* wdp  = wd + (size_t)e * I_DIM * H_DIM + n0;

    float acc[4][4][4];
#pragma unroll
    for (int i = 0; i < 4; i++)
#pragma unroll
        for (int j = 0; j < 4; j++)
#pragma unroll
            for (int q = 0; q < 4; q++) acc[i][j][q] = 0.f;

    float4 rA[4], rB[4];

#define G2_LOAD(k0)                                                                   \
    {                                                                                 \
        _Pragma("unroll")                                                             \
        for (int it = 0; it < 4; ++it) {                                              \
            int f = tid + it * 256;                                                   \
            int m = f >> 3, kq = (f & 7) << 2;                                        \
            int gp = m0 + m;                                                          \
            rA[it] = (gp < count)                                                     \
                ? *reinterpret_cast<const float4*>(actp + (size_t)gp * I_DIM + (k0) + kq) \
                : make_float4(0.f, 0.f, 0.f, 0.f);                                    \
        }                                                                             \
        _Pragma("unroll")                                                             \
        for (int it = 0; it < 4; ++it) {                                              \
            int f = tid + it * 256;                                                   \
            int k = f >> 5, nq = (f & 31) << 2;                                       \
            rB[it] = *reinterpret_cast<const float4*>(wdp + (size_t)((k0) + k) * H_DIM + nq); \
        }                                                                             \
    }

#define G2_STORE(s)                                                                   \
    {                                                                                 \
        float* As = sm + (s) * 8192;                                                  \
        float* Bs = As + 4096;                                                        \
        _Pragma("unroll")                                                             \
        for (int it = 0; it < 4; ++it) {                                              \
            int f = tid + it * 256;                                                   \
            int m = f >> 3, kq = (f & 7) << 2;                                        \
            int ks = kq >> 3, chalf = (kq >> 2) & 1;                                  \
            int reg = ((m >> 3) & 1) + 2 * chalf;                                     \
            int mt = m >> 4, lane0 = (m & 7) << 2;                                    \
            int idx = ((ks * 8 + mt) * 32 + lane0) * 4 + reg;                         \
            As[idx + 0]  = rA[it].x;  /* already tf32-rounded */                      \
            As[idx + 4]  = rA[it].y;                                                  \
            As[idx + 8]  = rA[it].z;                                                  \
            As[idx + 12] = rA[it].w;                                                  \
        }                                                                             \
        _Pragma("unroll")                                                             \
        for (int it = 0; it < 4; ++it) {                                              \
            int f = tid + it * 256;                                                   \
            int k = f >> 5, nq = (f & 31) << 2;                                       \
            int ks = k >> 3, reg = (k >> 2) & 1, lk = k & 3;                          \
            float vb[4] = {rB[it].x, rB[it].y, rB[it].z, rB[it].w};                   \
            _Pragma("unroll")                                                         \
            for (int i = 0; i < 4; ++i) {                                             \
                int n = nq + i;                                                       \
                int nt = n >> 3;                                                      \
                int ln = lk + ((n & 7) << 2);                                         \
                Bs[((ks * 16 + nt) * 32 + ln) * 2 + reg] = to_tf32f(vb[i]);           \
            }                                                                         \
        }                                                                             \
    }

#define G2_MMA(s)                                                                     \
    {                                                                                 \
        const float* As = sm + (s) * 8192;                                            \
        const float* Bs = As + 4096;                                                  \
        _Pragma("unroll")                                                             \
        for (int ks = 0; ks < 4; ++ks) {                                              \
            uint4 af[4];                                                              \
            _Pragma("unroll")                                                         \
            for (int mt = 0; mt < 4; ++mt)                                            \
                af[mt] = *reinterpret_cast<const uint4*>(                             \
                    As + ((ks * 8 + wm * 4 + mt) * 32 + lane) * 4);                   \
            uint2 bf[4];                                                              \
            _Pragma("unroll")                                                         \
            for (int nt = 0; nt < 4; ++nt)                                            \
                bf[nt] = *reinterpret_cast<const uint2*>(                             \
                    Bs + ((ks * 16 + wn * 4 + nt) * 32 + lane) * 2);                  \
            _Pragma("unroll")                                                         \
            for (int mt = 0; mt < 4; ++mt)                                            \
                _Pragma("unroll")                                                     \
                for (int nt = 0; nt < 4; ++nt)                                        \
                    mma_tf32(acc[mt][nt], (const uint32_t*)&af[mt], (const uint32_t*)&bf[nt]); \
        }                                                                             \
    }

    G2_LOAD(0);
    G2_STORE(0);
    __syncthreads();

    const int NC = I_DIM / 32;
    for (int c = 0; c < NC; ++c) {
        if (c + 1 < NC) G2_LOAD((c + 1) * 32);
        G2_MMA(c & 1);
        __syncthreads();
        if (c + 1 < NC) {
            G2_STORE((c + 1) & 1);
            __syncthreads();
        }
    }

    // ---- epilogue: scale by combine weight, write slot buffer ----
#pragma unroll
    for (int mt = 0; mt < 4; ++mt) {
        int row_base = wm * 64 + mt * 16 + (lane >> 2);
#pragma unroll
        for (int h = 0; h < 2; ++h) {
            int gpos = m0 + row_base + h * 8;
            if (gpos >= count) continue;
            float w = g_wt[e][gpos];
            float* dst = g_y + ((size_t)e * T_TOK + gpos) * H_DIM + n0;
#pragma unroll
            for (int nt = 0; nt < 4; ++nt) {
                int col = wn * 32 + nt * 8 + (lane & 3) * 2;
                float2 o;
                o.x = w * acc[mt][nt][2 * h];
                o.y = w * acc[mt][nt][2 * h + 1];
                *reinterpret_cast<float2*>(dst + col) = o;
            }
        }
    }
#undef G2_LOAD
#undef G2_STORE
#undef G2_MMA
}

// ---------------- combine: out[t] = y[slot0] + y[slot1] ----------------
__global__ __launch_bounds__(256) void combine_kernel(float* __restrict__ out) {
    int t = blockIdx.x;
    int s0 = g_slot[t][0], s1 = g_slot[t][1];
    const float4* y0 = reinterpret_cast<const float4*>(g_y + (size_t)s0 * H_DIM);
    const float4* y1 = reinterpret_cast<const float4*>(g_y + (size_t)s1 * H_DIM);
    float4* o = reinterpret_cast<float4*>(out + (size_t)t * H_DIM);
    int c = threadIdx.x;
    float4 a = y0[c], b = y1[c];
    o[c] = make_float4(a.x + b.x, a.y + b.y, a.z + b.z, a.w + b.w);
}

// ---------------- launch ----------------
extern "C" void kernel_launch(void* const* d_in, const int* in_sizes, int n_in,
                              void* d_out, int out_size) {
    const float* hs = (const float*)d_in[0];   // [T, H]
    const float* gw = (const float*)d_in[1];   // [H, E]
    const float* wg = (const float*)d_in[2];   // [E, H, I]
    const float* wu = (const float*)d_in[3];   // [E, H, I]
    const float* wd = (const float*)d_in[4];   // [E, I, H]
    float* out = (float*)d_out;                // [T, H]

    static bool attr_done = false;
    if (!attr_done) {
        cudaFuncSetAttribute(gemm1_kernel, cudaFuncAttributeMaxDynamicSharedMemorySize, 65536);
        cudaFuncSetAttribute(gemm2_kernel, cudaFuncAttributeMaxDynamicSharedMemorySize, 65536);
        attr_done = true;
    }

    zero_counts_kernel<<<1, 32>>>();
    router_kernel<<<T_TOK, 128>>>(hs, gw);

    dim3 g1(I_DIM / 64, T_TOK / 128, E_NUM);    // (32, 16, 8)
    gemm1_kernel<<<g1, 256, 65536>>>(hs, wg, wu);

    dim3 g2(H_DIM / 128, T_TOK / 128, E_NUM);   // (8, 16, 8)
    gemm2_kernel<<<g2, 256, 65536>>>(wd);

    combine_kernel<<<T_TOK, 256>>>(out);
}

// round 4
// speedup vs baseline: 1.7815x; 1.6273x over previous
#include <cuda_runtime.h>
#include <math.h>
#include <stdint.h>

#define T_TOK 2048
#define H_DIM 1024
#define E_NUM 8
#define I_DIM 2048

// ---------------- device scratch ----------------
__device__ int   g_count[E_NUM];
__device__ int   g_tok[E_NUM][T_TOK];
__device__ float g_wt[E_NUM][T_TOK];
__device__ int   g_slot[T_TOK][2];
__device__ float g_act[(size_t)E_NUM * T_TOK * I_DIM];   // 128 MB (tf32-rounded values)
__device__ float g_y[(size_t)E_NUM * T_TOK * H_DIM];     // 64 MB

// ---------------- helpers ----------------
__device__ __forceinline__ uint32_t to_tf32(float x) {
    uint32_t r; asm("cvt.rna.tf32.f32 %0, %1;" : "=r"(r) : "f"(x)); return r;
}
__device__ __forceinline__ float to_tf32f(float x) {
    return __uint_as_float(to_tf32(x));
}
__device__ __forceinline__ void mma_tf32(float* c, const uint32_t* a, const uint32_t* b) {
    asm volatile(
        "mma.sync.aligned.m16n8k8.row.col.f32.tf32.tf32.f32 "
        "{%0,%1,%2,%3}, {%4,%5,%6,%7}, {%8,%9}, {%0,%1,%2,%3};"
        : "+f"(c[0]), "+f"(c[1]), "+f"(c[2]), "+f"(c[3])
        : "r"(a[0]), "r"(a[1]), "r"(a[2]), "r"(a[3]), "r"(b[0]), "r"(b[1]));
}

// ---------------- small kernels ----------------
__global__ void zero_counts_kernel() {
    if (threadIdx.x < E_NUM) g_count[threadIdx.x] = 0;
}

__global__ void router_kernel(const float* __restrict__ hs, const float* __restrict__ gw) {
    int t = blockIdx.x;
    const float* x = hs + (size_t)t * H_DIM;
    float acc[E_NUM];
#pragma unroll
    for (int e = 0; e < E_NUM; e++) acc[e] = 0.f;
    for (int j = threadIdx.x; j < H_DIM; j += blockDim.x) {
        float xv = x[j];
        const float4* grow = reinterpret_cast<const float4*>(gw + (size_t)j * E_NUM);
        float4 g0 = grow[0], g1 = grow[1];
        acc[0] += xv * g0.x; acc[1] += xv * g0.y; acc[2] += xv * g0.z; acc[3] += xv * g0.w;
        acc[4] += xv * g1.x; acc[5] += xv * g1.y; acc[6] += xv * g1.z; acc[7] += xv * g1.w;
    }
#pragma unroll
    for (int off = 16; off > 0; off >>= 1)
#pragma unroll
        for (int e = 0; e < E_NUM; e++)
            acc[e] += __shfl_xor_sync(0xffffffffu, acc[e], off);
    __shared__ float s[4][E_NUM];
    int warp = threadIdx.x >> 5, lane = threadIdx.x & 31;
    if (lane == 0)
#pragma unroll
        for (int e = 0; e < E_NUM; e++) s[warp][e] = acc[e];
    __syncthreads();
    if (threadIdx.x == 0) {
        float l[E_NUM];
#pragma unroll
        for (int e = 0; e < E_NUM; e++)
            l[e] = tanhf((s[0][e] + s[1][e] + s[2][e] + s[3][e]) * (1.0f / 30.0f));
        int i0 = 0;
#pragma unroll
        for (int e = 1; e < E_NUM; e++) if (l[e] > l[i0]) i0 = e;
        int i1 = (i0 == 0) ? 1 : 0;
#pragma unroll
        for (int e = 0; e < E_NUM; e++) if (e != i0 && l[e] > l[i1]) i1 = e;
        float d  = l[i1] - l[i0];
        float ed = expf(d);
        float inv = 1.0f / (1.0f + ed);
        float p0 = inv, p1 = ed * inv;
        int p = atomicAdd(&g_count[i0], 1);
        g_tok[i0][p] = t; g_wt[i0][p] = p0; g_slot[t][0] = i0 * T_TOK + p;
        p = atomicAdd(&g_count[i1], 1);
        g_tok[i1][p] = t; g_wt[i1][p] = p1; g_slot[t][1] = i1 * T_TOK + p;
    }
}

__device__ __forceinline__ float gelu_tanh(float g) {
    float c = 0.7978845608028654f * (g + 0.044715f * g * g * g);
    return 0.5f * g * (1.0f + tanhf(c));
}

// ============================================================================
// GEMM1: act = tf32( gelu(X@wg) * (X@wu) )   [per expert, gathered rows]
// CTA tile: M=128 x N=64 (both g and u). K=1024, kb=32, double-buffered.
// B loader: thread f owns slot (ks=f>>8, nt=(f>>5)&7, ln=f&31);
//   n = nt*8 + (ln>>2), k = ks*8 + (ln&3) (+4 for second reg)
//   -> one conflict-free STS.64 per slot per matrix.
// ============================================================================
__global__ __launch_bounds__(256, 1)
void gemm1_kernel(const float* __restrict__ hs,
                  const float* __restrict__ wg,
                  const float* __restrict__ wu) {
    const int e = blockIdx.z;
    const int count = g_count[e];
    const int m0 = blockIdx.y * 128;
    if (m0 >= count) return;
    const int n0 = blockIdx.x * 64;

    extern __shared__ float sm[];
    __shared__ int rowtok[128];

    const int tid = threadIdx.x, wid = tid >> 5, lane = tid & 31;
    const int wm = wid & 1, wn = wid >> 1;

    if (tid < 128) {
        int gp = m0 + tid;
        rowtok[tid] = (gp < count) ? g_tok[e][gp] : -1;
    }
    __syncthreads();

    const float* wgp = wg + (size_t)e * H_DIM * I_DIM + n0;
    const float* wup = wu + (size_t)e * H_DIM * I_DIM + n0;

    float accg[4][2][4], accu[4][2][4];
#pragma unroll
    for (int i = 0; i < 4; i++)
#pragma unroll
        for (int j = 0; j < 2; j++)
#pragma unroll
            for (int q = 0; q < 4; q++) { accg[i][j][q] = 0.f; accu[i][j][q] = 0.f; }

    float4 rA[4];
    float2 rBg[4], rBu[4];

#define G1_LOAD(k0)                                                                   \
    {                                                                                 \
        _Pragma("unroll")                                                             \
        for (int it = 0; it < 4; ++it) {                                              \
            int f = tid + it * 256;                                                   \
            int m = f >> 3, kq = (f & 7) << 2;                                        \
            int tok = rowtok[m];                                                      \
            rA[it] = (tok >= 0)                                                       \
                ? *reinterpret_cast<const float4*>(hs + (size_t)tok * H_DIM + (k0) + kq) \
                : make_float4(0.f, 0.f, 0.f, 0.f);                                    \
        }                                                                             \
        _Pragma("unroll")                                                             \
        for (int it = 0; it < 4; ++it) {                                              \
            int f = tid + it * 256;                                                   \
            int ln = f & 31, nt = (f >> 5) & 7, ks = f >> 8;                          \
            int n = nt * 8 + (ln >> 2);                                               \
            int k = ks * 8 + (ln & 3);                                                \
            const float* pg = wgp + (size_t)((k0) + k) * I_DIM + n;                   \
            const float* pu = wup + (size_t)((k0) + k) * I_DIM + n;                   \
            rBg[it].x = pg[0];           rBg[it].y = pg[4 * I_DIM];                   \
            rBu[it].x = pu[0];           rBu[it].y = pu[4 * I_DIM];                   \
        }                                                                             \
    }

#define G1_STORE(s)                                                                   \
    {                                                                                 \
        float* As = sm + (s) * 8192;                                                  \
        float* Bgs = As + 4096;                                                       \
        float* Bus = As + 6144;                                                       \
        _Pragma("unroll")                                                             \
        for (int it = 0; it < 4; ++it) {                                              \
            int f = tid + it * 256;                                                   \
            int m = f >> 3, kq = (f & 7) << 2;                                        \
            int ks = kq >> 3, chalf = (kq >> 2) & 1;                                  \
            int reg = ((m >> 3) & 1) + 2 * chalf;                                     \
            int mt = m >> 4, lane0 = (m & 7) << 2;                                    \
            int idx = ((ks * 8 + mt) * 32 + lane0) * 4 + reg;                         \
            As[idx + 0]  = to_tf32f(rA[it].x);                                        \
            As[idx + 4]  = to_tf32f(rA[it].y);                                        \
            As[idx + 8]  = to_tf32f(rA[it].z);                                        \
            As[idx + 12] = to_tf32f(rA[it].w);                                        \
        }                                                                             \
        _Pragma("unroll")                                                             \
        for (int it = 0; it < 4; ++it) {                                              \
            int f = tid + it * 256;                                                   \
            int ln = f & 31, nt = (f >> 5) & 7, ks = f >> 8;                          \
            int idx = ((ks * 8 + nt) * 32 + ln) * 2;                                  \
            *reinterpret_cast<float2*>(Bgs + idx) =                                   \
                make_float2(to_tf32f(rBg[it].x), to_tf32f(rBg[it].y));                \
            *reinterpret_cast<float2*>(Bus + idx) =                                   \
                make_float2(to_tf32f(rBu[it].x), to_tf32f(rBu[it].y));                \
        }                                                                             \
    }

#define G1_MMA(s)                                                                     \
    {                                                                                 \
        const float* As = sm + (s) * 8192;                                            \
        const float* Bgs = As + 4096;                                                 \
        const float* Bus = As + 6144;                                                 \
        _Pragma("unroll")                                                             \
        for (int ks = 0; ks < 4; ++ks) {                                              \
            uint4 af[4];                                                              \
            _Pragma("unroll")                                                         \
            for (int mt = 0; mt < 4; ++mt)                                            \
                af[mt] = *reinterpret_cast<const uint4*>(                             \
                    As + ((ks * 8 + wm * 4 + mt) * 32 + lane) * 4);                   \
            uint2 bgf[2], buf_[2];                                                    \
            _Pragma("unroll")                                                         \
            for (int nt = 0; nt < 2; ++nt) {                                          \
                bgf[nt] = *reinterpret_cast<const uint2*>(                            \
                    Bgs + ((ks * 8 + wn * 2 + nt) * 32 + lane) * 2);                  \
                buf_[nt] = *reinterpret_cast<const uint2*>(                           \
                    Bus + ((ks * 8 + wn * 2 + nt) * 32 + lane) * 2);                  \
            }                                                                         \
            _Pragma("unroll")                                                         \
            for (int mt = 0; mt < 4; ++mt)                                            \
                _Pragma("unroll")                                                     \
                for (int nt = 0; nt < 2; ++nt) {                                      \
                    mma_tf32(accg[mt][nt], (const uint32_t*)&af[mt], (const uint32_t*)&bgf[nt]); \
                    mma_tf32(accu[mt][nt], (const uint32_t*)&af[mt], (const uint32_t*)&buf_[nt]); \
                }                                                                     \
        }                                                                             \
    }

    G1_LOAD(0);
    G1_STORE(0);
    __syncthreads();

    const int NC = H_DIM / 32;
    for (int c = 0; c < NC; ++c) {
        if (c + 1 < NC) G1_LOAD((c + 1) * 32);
        G1_MMA(c & 1);
        __syncthreads();
        if (c + 1 < NC) {
            G1_STORE((c + 1) & 1);
            __syncthreads();
        }
    }

    // ---- epilogue: fused gelu(g)*u, pre-rounded to tf32 for GEMM2 ----
#pragma unroll
    for (int mt = 0; mt < 4; ++mt) {
        int row_base = wm * 64 + mt * 16 + (lane >> 2);
#pragma unroll
        for (int nt = 0; nt < 2; ++nt) {
            int col = wn * 16 + nt * 8 + (lane & 3) * 2;
#pragma unroll
            for (int h = 0; h < 2; ++h) {
                int gpos = m0 + row_base + h * 8;
                if (gpos < count) {
                    float gv0 = accg[mt][nt][2 * h], gv1 = accg[mt][nt][2 * h + 1];
                    float uv0 = accu[mt][nt][2 * h], uv1 = accu[mt][nt][2 * h + 1];
                    float2 o;
                    o.x = to_tf32f(gelu_tanh(gv0) * uv0);
                    o.y = to_tf32f(gelu_tanh(gv1) * uv1);
                    *reinterpret_cast<float2*>(
                        g_act + ((size_t)e * T_TOK + gpos) * I_DIM + n0 + col) = o;
                }
            }
        }
    }
#undef G1_LOAD
#undef G1_STORE
#undef G1_MMA
}

// ============================================================================
// GEMM2: y = weight * (act @ wd)   [per expert]
// CTA tile: M=128 x N=128. K=2048, kb=32, double-buffered.
// B loader: thread f owns slot (ks=f>>9, nt=(f>>5)&15, ln=f&31) -> STS.64
// ============================================================================
__global__ __launch_bounds__(256, 1)
void gemm2_kernel(const float* __restrict__ wd) {
    const int e = blockIdx.z;
    const int count = g_count[e];
    const int m0 = blockIdx.y * 128;
    if (m0 >= count) return;
    const int n0 = blockIdx.x * 128;

    extern __shared__ float sm[];

    const int tid = threadIdx.x, wid = tid >> 5, lane = tid & 31;
    const int wm = wid & 1, wn = wid >> 1;

    const float* actp = g_act + (size_t)e * T_TOK * I_DIM;
    const float* wdp  = wd + (size_t)e * I_DIM * H_DIM + n0;

    float acc[4][4][4];
#pragma unroll
    for (int i = 0; i < 4; i++)
#pragma unroll
        for (int j = 0; j < 4; j++)
#pragma unroll
            for (int q = 0; q < 4; q++) acc[i][j][q] = 0.f;

    float4 rA[4];
    float2 rB[8];

#define G2_LOAD(k0)                                                                   \
    {                                                                                 \
        _Pragma("unroll")                                                             \
        for (int it = 0; it < 4; ++it) {                                              \
            int f = tid + it * 256;                                                   \
            int m = f >> 3, kq = (f & 7) << 2;                                        \
            int gp = m0 + m;                                                          \
            rA[it] = (gp < count)                                                     \
                ? *reinterpret_cast<const float4*>(actp + (size_t)gp * I_DIM + (k0) + kq) \
                : make_float4(0.f, 0.f, 0.f, 0.f);                                    \
        }                                                                             \
        _Pragma("unroll")                                                             \
        for (int it = 0; it < 8; ++it) {                                              \
            int f = tid + it * 256;                                                   \
            int ln = f & 31, nt = (f >> 5) & 15, ks = f >> 9;                         \
            int n = nt * 8 + (ln >> 2);                                               \
            int k = ks * 8 + (ln & 3);                                                \
            const float* pb = wdp + (size_t)((k0) + k) * H_DIM + n;                   \
            rB[it].x = pb[0];            rB[it].y = pb[4 * H_DIM];                    \
        }                                                                             \
    }

#define G2_STORE(s)                                                                   \
    {                                                                                 \
        float* As = sm + (s) * 8192;                                                  \
        float* Bs = As + 4096;                                                        \
        _Pragma("unroll")                                                             \
        for (int it = 0; it < 4; ++it) {                                              \
            int f = tid + it * 256;                                                   \
            int m = f >> 3, kq = (f & 7) << 2;                                        \
            int ks = kq >> 3, chalf = (kq >> 2) & 1;                                  \
            int reg = ((m >> 3) & 1) + 2 * chalf;                                     \
            int mt = m >> 4, lane0 = (m & 7) << 2;                                    \
            int idx = ((ks * 8 + mt) * 32 + lane0) * 4 + reg;                         \
            As[idx + 0]  = rA[it].x;  /* already tf32-rounded */                      \
            As[idx + 4]  = rA[it].y;                                                  \
            As[idx + 8]  = rA[it].z;                                                  \
            As[idx + 12] = rA[it].w;                                                  \
        }                                                                             \
        _Pragma("unroll")                                                             \
        for (int it = 0; it < 8; ++it) {                                              \
            int f = tid + it * 256;                                                   \
            int ln = f & 31, nt = (f >> 5) & 15, ks = f >> 9;                         \
            *reinterpret_cast<float2*>(Bs + ((ks * 16 + nt) * 32 + ln) * 2) =         \
                make_float2(to_tf32f(rB[it].x), to_tf32f(rB[it].y));                  \
        }                                                                             \
    }

#define G2_MMA(s)                                                                     \
    {                                                                                 \
        const float* As = sm + (s) * 8192;                                            \
        const float* Bs = As + 4096;                                                  \
        _Pragma("unroll")                                                             \
        for (int ks = 0; ks < 4; ++ks) {                                              \
            uint4 af[4];                                                              \
            _Pragma("unroll")                                                         \
            for (int mt = 0; mt < 4; ++mt)                                            \
                af[mt] = *reinterpret_cast<const uint4*>(                             \
                    As + ((ks * 8 + wm * 4 + mt) * 32 + lane) * 4);                   \
            uint2 bf[4];                                                              \
            _Pragma("unroll")                                                         \
            for (int nt = 0; nt < 4; ++nt)                                            \
                bf[nt] = *reinterpret_cast<const uint2*>(                             \
                    Bs + ((ks * 16 + wn * 4 + nt) * 32 + lane) * 2);                  \
            _Pragma("unroll")                                                         \
            for (int mt = 0; mt < 4; ++mt)                                            \
                _Pragma("unroll")                                                     \
                for (int nt = 0; nt < 4; ++nt)                                        \
                    mma_tf32(acc[mt][nt], (const uint32_t*)&af[mt], (const uint32_t*)&bf[nt]); \
        }                                                                             \
    }

    G2_LOAD(0);
    G2_STORE(0);
    __syncthreads();

    const int NC = I_DIM / 32;
    for (int c = 0; c < NC; ++c) {
        if (c + 1 < NC) G2_LOAD((c + 1) * 32);
        G2_MMA(c & 1);
        __syncthreads();
        if (c + 1 < NC) {
            G2_STORE((c + 1) & 1);
            __syncthreads();
        }
    }

    // ---- epilogue: scale by combine weight, write slot buffer ----
#pragma unroll
    for (int mt = 0; mt < 4; ++mt) {
        int row_base = wm * 64 + mt * 16 + (lane >> 2);
#pragma unroll
        for (int h = 0; h < 2; ++h) {
            int gpos = m0 + row_base + h * 8;
            if (gpos >= count) continue;
            float w = g_wt[e][gpos];
            float* dst = g_y + ((size_t)e * T_TOK + gpos) * H_DIM + n0;
#pragma unroll
            for (int nt = 0; nt < 4; ++nt) {
                int col = wn * 32 + nt * 8 + (lane & 3) * 2;
                float2 o;
                o.x = w * acc[mt][nt][2 * h];
                o.y = w * acc[mt][nt][2 * h + 1];
                *reinterpret_cast<float2*>(dst + col) = o;
            }
        }
    }
#undef G2_LOAD
#undef G2_STORE
#undef G2_MMA
}

// ---------------- combine: out[t] = y[slot0] + y[slot1] ----------------
__global__ __launch_bounds__(256) void combine_kernel(float* __restrict__ out) {
    int t = blockIdx.x;
    int s0 = g_slot[t][0], s1 = g_slot[t][1];
    const float4* y0 = reinterpret_cast<const float4*>(g_y + (size_t)s0 * H_DIM);
    const float4* y1 = reinterpret_cast<const float4*>(g_y + (size_t)s1 * H_DIM);
    float4* o = reinterpret_cast<float4*>(out + (size_t)t * H_DIM);
    int c = threadIdx.x;
    float4 a = y0[c], b = y1[c];
    o[c] = make_float4(a.x + b.x, a.y + b.y, a.z + b.z, a.w + b.w);
}

// ---------------- launch ----------------
extern "C" void kernel_launch(void* const* d_in, const int* in_sizes, int n_in,
                              void* d_out, int out_size) {
    const float* hs = (const float*)d_in[0];   // [T, H]
    const float* gw = (const float*)d_in[1];   // [H, E]
    const float* wg = (const float*)d_in[2];   // [E, H, I]
    const float* wu = (const float*)d_in[3];   // [E, H, I]
    const float* wd = (const float*)d_in[4];   // [E, I, H]
    float* out = (float*)d_out;                // [T, H]

    static bool attr_done = false;
    if (!attr_done) {
        cudaFuncSetAttribute(gemm1_kernel, cudaFuncAttributeMaxDynamicSharedMemorySize, 65536);
        cudaFuncSetAttribute(gemm2_kernel, cudaFuncAttributeMaxDynamicSharedMemorySize, 65536);
        attr_done = true;
    }

    zero_counts_kernel<<<1, 32>>>();
    router_kernel<<<T_TOK, 128>>>(hs, gw);

    dim3 g1(I_DIM / 64, T_TOK / 128, E_NUM);    // (32, 16, 8)
    gemm1_kernel<<<g1, 256, 65536>>>(hs, wg, wu);

    dim3 g2(H_DIM / 128, T_TOK / 128, E_NUM);   // (8, 16, 8)
    gemm2_kernel<<<g2, 256, 65536>>>(wd);

    combine_kernel<<<T_TOK, 256>>>(out);
}

// round 6
// speedup vs baseline: 1.9424x; 1.0903x over previous
#include <cuda_runtime.h>
#include <math.h>
#include <stdint.h>

#define T_TOK 2048
#define H_DIM 1024
#define E_NUM 8
#define I_DIM 2048

// ---------------- device scratch ----------------
__device__ int   g_count[E_NUM];
__device__ int   g_tok[E_NUM][T_TOK];
__device__ float g_wt[E_NUM][T_TOK];
__device__ int   g_slot[T_TOK][2];
__device__ float g_act[(size_t)E_NUM * T_TOK * I_DIM];   // 128 MB (tf32-rounded values)
__device__ float g_y[(size_t)E_NUM * T_TOK * H_DIM];     // 64 MB

// ---------------- helpers ----------------
__device__ __forceinline__ uint32_t to_tf32(float x) {
    uint32_t r; asm("cvt.rna.tf32.f32 %0, %1;" : "=r"(r) : "f"(x)); return r;
}
__device__ __forceinline__ float to_tf32f(float x) {
    return __uint_as_float(to_tf32(x));
}
__device__ __forceinline__ void mma_tf32(float* c, const uint32_t* a, const uint32_t* b) {
    asm volatile(
        "mma.sync.aligned.m16n8k8.row.col.f32.tf32.tf32.f32 "
        "{%0,%1,%2,%3}, {%4,%5,%6,%7}, {%8,%9}, {%0,%1,%2,%3};"
        : "+f"(c[0]), "+f"(c[1]), "+f"(c[2]), "+f"(c[3])
        : "r"(a[0]), "r"(a[1]), "r"(a[2]), "r"(a[3]), "r"(b[0]), "r"(b[1]));
}

// ---------------- small kernels ----------------
__global__ void zero_counts_kernel() {
    if (threadIdx.x < E_NUM) g_count[threadIdx.x] = 0;
}

__global__ void router_kernel(const float* __restrict__ hs, const float* __restrict__ gw) {
    int t = blockIdx.x;
    const float* x = hs + (size_t)t * H_DIM;
    float acc[E_NUM];
#pragma unroll
    for (int e = 0; e < E_NUM; e++) acc[e] = 0.f;
    for (int j = threadIdx.x; j < H_DIM; j += blockDim.x) {
        float xv = x[j];
        const float4* grow = reinterpret_cast<const float4*>(gw + (size_t)j * E_NUM);
        float4 g0 = grow[0], g1 = grow[1];
        acc[0] += xv * g0.x; acc[1] += xv * g0.y; acc[2] += xv * g0.z; acc[3] += xv * g0.w;
        acc[4] += xv * g1.x; acc[5] += xv * g1.y; acc[6] += xv * g1.z; acc[7] += xv * g1.w;
    }
#pragma unroll
    for (int off = 16; off > 0; off >>= 1)
#pragma unroll
        for (int e = 0; e < E_NUM; e++)
            acc[e] += __shfl_xor_sync(0xffffffffu, acc[e], off);
    __shared__ float s[4][E_NUM];
    int warp = threadIdx.x >> 5, lane = threadIdx.x & 31;
    if (lane == 0)
#pragma unroll
        for (int e = 0; e < E_NUM; e++) s[warp][e] = acc[e];
    __syncthreads();
    if (threadIdx.x == 0) {
        float l[E_NUM];
#pragma unroll
        for (int e = 0; e < E_NUM; e++)
            l[e] = tanhf((s[0][e] + s[1][e] + s[2][e] + s[3][e]) * (1.0f / 30.0f));
        int i0 = 0;
#pragma unroll
        for (int e = 1; e < E_NUM; e++) if (l[e] > l[i0]) i0 = e;
        int i1 = (i0 == 0) ? 1 : 0;
#pragma unroll
        for (int e = 0; e < E_NUM; e++) if (e != i0 && l[e] > l[i1]) i1 = e;
        float d  = l[i1] - l[i0];
        float ed = expf(d);
        float inv = 1.0f / (1.0f + ed);
        float p0 = inv, p1 = ed * inv;
        int p = atomicAdd(&g_count[i0], 1);
        g_tok[i0][p] = t; g_wt[i0][p] = p0; g_slot[t][0] = i0 * T_TOK + p;
        p = atomicAdd(&g_count[i1], 1);
        g_tok[i1][p] = t; g_wt[i1][p] = p1; g_slot[t][1] = i1 * T_TOK + p;
    }
}

__device__ __forceinline__ float gelu_tanh(float g) {
    float c = 0.7978845608028654f * (g + 0.044715f * g * g * g);
    return 0.5f * g * (1.0f + tanhf(c));
}

// ============================================================================
// GEMM1: act = tf32( gelu(X@wg) * (X@wu) )   [per expert, gathered rows]
// CTA tile: M=128 x N=64 (both g and u). K=1024, kb=16, double-buffered,
// 2 CTAs/SM. Stage = A 2048 + Bg 1024 + Bu 1024 = 4096 floats (16KB).
// ============================================================================
__global__ __launch_bounds__(256, 2)
void gemm1_kernel(const float* __restrict__ hs,
                  const float* __restrict__ wg,
                  const float* __restrict__ wu) {
    const int e = blockIdx.z;
    const int count = g_count[e];
    const int m0 = blockIdx.y * 128;
    if (m0 >= count) return;
    const int n0 = blockIdx.x * 64;

    __shared__ float sm[2 * 4096];
    __shared__ int rowtok[128];

    const int tid = threadIdx.x, wid = tid >> 5, lane = tid & 31;
    const int wm = wid & 1, wn = wid >> 1;

    if (tid < 128) {
        int gp = m0 + tid;
        rowtok[tid] = (gp < count) ? g_tok[e][gp] : -1;
    }
    __syncthreads();

    const float* wgp = wg + (size_t)e * H_DIM * I_DIM + n0;
    const float* wup = wu + (size_t)e * H_DIM * I_DIM + n0;

    float accg[4][2][4], accu[4][2][4];
#pragma unroll
    for (int i = 0; i < 4; i++)
#pragma unroll
        for (int j = 0; j < 2; j++)
#pragma unroll
            for (int q = 0; q < 4; q++) { accg[i][j][q] = 0.f; accu[i][j][q] = 0.f; }

    float4 rA[2];
    float2 rBg[2], rBu[2];

#define G1_LOAD(k0)                                                                   \
    {                                                                                 \
        _Pragma("unroll")                                                             \
        for (int it = 0; it < 2; ++it) {                                              \
            int f = tid + it * 256;                                                   \
            int m = f >> 2, kq = (f & 3) << 2;                                        \
            int tok = rowtok[m];                                                      \
            rA[it] = (tok >= 0)                                                       \
                ? *reinterpret_cast<const float4*>(hs + (size_t)tok * H_DIM + (k0) + kq) \
                : make_float4(0.f, 0.f, 0.f, 0.f);                                    \
        }                                                                             \
        _Pragma("unroll")                                                             \
        for (int it = 0; it < 2; ++it) {                                              \
            int f = tid + it * 256;                                                   \
            int ln = f & 31, nt = (f >> 5) & 7, ks = (f >> 8) & 1;                    \
            int n = nt * 8 + (ln >> 2);                                               \
            int k = ks * 8 + (ln & 3);                                                \
            const float* pg = wgp + (size_t)((k0) + k) * I_DIM + n;                   \
            const float* pu = wup + (size_t)((k0) + k) * I_DIM + n;                   \
            rBg[it].x = pg[0];           rBg[it].y = pg[4 * I_DIM];                   \
            rBu[it].x = pu[0];           rBu[it].y = pu[4 * I_DIM];                   \
        }                                                                             \
    }

#define G1_STORE(s)                                                                   \
    {                                                                                 \
        float* As = sm + (s) * 4096;                                                  \
        float* Bgs = As + 2048;                                                       \
        float* Bus = As + 3072;                                                       \
        _Pragma("unroll")                                                             \
        for (int it = 0; it < 2; ++it) {                                              \
            int f = tid + it * 256;                                                   \
            int m = f >> 2, kq = (f & 3) << 2;                                        \
            int ks = kq >> 3, chalf = (kq >> 2) & 1;                                  \
            int reg = ((m >> 3) & 1) + 2 * chalf;                                     \
            int mt = m >> 4, lane0 = (m & 7) << 2;                                    \
            int idx = ((ks * 8 + mt) * 32 + lane0) * 4 + reg;                         \
            As[idx + 0]  = to_tf32f(rA[it].x);                                        \
            As[idx + 4]  = to_tf32f(rA[it].y);                                        \
            As[idx + 8]  = to_tf32f(rA[it].z);                                        \
            As[idx + 12] = to_tf32f(rA[it].w);                                        \
        }                                                                             \
        _Pragma("unroll")                                                             \
        for (int it = 0; it < 2; ++it) {                                              \
            int f = tid + it * 256;                                                   \
            int ln = f & 31, nt = (f >> 5) & 7, ks = (f >> 8) & 1;                    \
            int idx = ((ks * 8 + nt) * 32 + ln) * 2;                                  \
            *reinterpret_cast<float2*>(Bgs + idx) =                                   \
                make_float2(to_tf32f(rBg[it].x), to_tf32f(rBg[it].y));                \
            *reinterpret_cast<float2*>(Bus + idx) =                                   \
                make_float2(to_tf32f(rBu[it].x), to_tf32f(rBu[it].y));                \
        }                                                                             \
    }

#define G1_MMA(s)                                                                     \
    {                                                                                 \
        const float* As = sm + (s) * 4096;                                            \
        const float* Bgs = As + 2048;                                                 \
        const float* Bus = As + 3072;                                                 \
        _Pragma("unroll")                                                             \
        for (int ks = 0; ks < 2; ++ks) {                                              \
            uint4 af[4];                                                              \
            _Pragma("unroll")                                                         \
            for (int mt = 0; mt < 4; ++mt)                                            \
                af[mt] = *reinterpret_cast<const uint4*>(                             \
                    As + ((ks * 8 + wm * 4 + mt) * 32 + lane) * 4);                   \
            uint2 bgf[2], buf_[2];                                                    \
            _Pragma("unroll")                                                         \
            for (int nt = 0; nt < 2; ++nt) {                                          \
                bgf[nt] = *reinterpret_cast<const uint2*>(                            \
                    Bgs + ((ks * 8 + wn * 2 + nt) * 32 + lane) * 2);                  \
                buf_[nt] = *reinterpret_cast<const uint2*>(                           \
                    Bus + ((ks * 8 + wn * 2 + nt) * 32 + lane) * 2);                  \
            }                                                                         \
            _Pragma("unroll")                                                         \
            for (int mt = 0; mt < 4; ++mt)                                            \
                _Pragma("unroll")                                                     \
                for (int nt = 0; nt < 2; ++nt) {                                      \
                    mma_tf32(accg[mt][nt], (const uint32_t*)&af[mt], (const uint32_t*)&bgf[nt]); \
                    mma_tf32(accu[mt][nt], (const uint32_t*)&af[mt], (const uint32_t*)&buf_[nt]); \
                }                                                                     \
        }                                                                             \
    }

    G1_LOAD(0);
    G1_STORE(0);
    __syncthreads();

    const int NC = H_DIM / 16;
    for (int c = 0; c < NC; ++c) {
        if (c + 1 < NC) G1_LOAD((c + 1) * 16);
        G1_MMA(c & 1);
        __syncthreads();
        if (c + 1 < NC) {
            G1_STORE((c + 1) & 1);
            __syncthreads();
        }
    }

    // ---- epilogue: fused gelu(g)*u, pre-rounded to tf32 for GEMM2 ----
#pragma unroll
    for (int mt = 0; mt < 4; ++mt) {
        int row_base = wm * 64 + mt * 16 + (lane >> 2);
#pragma unroll
        for (int nt = 0; nt < 2; ++nt) {
            int col = wn * 16 + nt * 8 + (lane & 3) * 2;
#pragma unroll
            for (int h = 0; h < 2; ++h) {
                int gpos = m0 + row_base + h * 8;
                if (gpos < count) {
                    float gv0 = accg[mt][nt][2 * h], gv1 = accg[mt][nt][2 * h + 1];
                    float uv0 = accu[mt][nt][2 * h], uv1 = accu[mt][nt][2 * h + 1];
                    float2 o;
                    o.x = to_tf32f(gelu_tanh(gv0) * uv0);
                    o.y = to_tf32f(gelu_tanh(gv1) * uv1);
                    *reinterpret_cast<float2*>(
                        g_act + ((size_t)e * T_TOK + gpos) * I_DIM + n0 + col) = o;
                }
            }
        }
    }
#undef G1_LOAD
#undef G1_STORE
#undef G1_MMA
}

// ============================================================================
// GEMM2: y = weight * (act @ wd)   [per expert]
// CTA tile: M=128 x N=128. K=2048, kb=16, double-buffered, 2 CTAs/SM.
// Stage = A 2048 + B 2048 = 4096 floats (16KB).
// ============================================================================
__global__ __launch_bounds__(256, 2)
void gemm2_kernel(const float* __restrict__ wd) {
    const int e = blockIdx.z;
    const int count = g_count[e];
    const int m0 = blockIdx.y * 128;
    if (m0 >= count) return;
    const int n0 = blockIdx.x * 128;

    __shared__ float sm[2 * 4096];

    const int tid = threadIdx.x, wid = tid >> 5, lane = tid & 31;
    const int wm = wid & 1, wn = wid >> 1;

    const float* actp = g_act + (size_t)e * T_TOK * I_DIM;
    const float* wdp  = wd + (size_t)e * I_DIM * H_DIM + n0;

    float acc[4][4][4];
#pragma unroll
    for (int i = 0; i < 4; i++)
#pragma unroll
        for (int j = 0; j < 4; j++)
#pragma unroll
            for (int q = 0; q < 4; q++) acc[i][j][q] = 0.f;

    float4 rA[2];
    float2 rB[4];

#define G2_LOAD(k0)                                                                   \
    {                                                                                 \
        _Pragma("unroll")                                                             \
        for (int it = 0; it < 2; ++it) {                                              \
            int f = tid + it * 256;                                                   \
            int m = f >> 2, kq = (f & 3) << 2;                                        \
            int gp = m0 + m;                                                          \
            rA[it] = (gp < count)                                                     \
                ? *reinterpret_cast<const float4*>(actp + (size_t)gp * I_DIM + (k0) + kq) \
                : make_float4(0.f, 0.f, 0.f, 0.f);                                    \
        }                                                                             \
        _Pragma("unroll")                                                             \
        for (int it = 0; it < 4; ++it) {                                              \
            int f = tid + it * 256;                                                   \
            int ln = f & 31, nt = (f >> 5) & 15, ks = (f >> 9) & 1;                   \
            int n = nt * 8 + (ln >> 2);                                               \
            int k = ks * 8 + (ln & 3);                                                \
            const float* pb = wdp + (size_t)((k0) + k) * H_DIM + n;                   \
            rB[it].x = pb[0];            rB[it].y = pb[4 * H_DIM];                    \
        }                                                                             \
    }

#define G2_STORE(s)                                                                   \
    {                                                                                 \
        float* As = sm + (s) * 4096;                                                  \
        float* Bs = As + 2048;                                                        \
        _Pragma("unroll")                                                             \
        for (int it = 0; it < 2; ++it) {                                              \
            int f = tid + it * 256;                                                   \
            int m = f >> 2, kq = (f & 3) << 2;                                        \
            int ks = kq >> 3, chalf = (kq >> 2) & 1;                                  \
            int reg = ((m >> 3) & 1) + 2 * chalf;                                     \
            int mt = m >> 4, lane0 = (m & 7) << 2;                                    \
            int idx = ((ks * 8 + mt) * 32 + lane0) * 4 + reg;                         \
            As[idx + 0]  = rA[it].x;  /* already tf32-rounded */                      \
            As[idx + 4]  = rA[it].y;                                                  \
            As[idx + 8]  = rA[it].z;                                                  \
            As[idx + 12] = rA[it].w;                                                  \
        }                                                                             \
        _Pragma("unroll")                                                             \
        for (int it = 0; it < 4; ++it) {                                              \
            int f = tid + it * 256;                                                   \
            int ln = f & 31, nt = (f >> 5) & 15, ks = (f >> 9) & 1;                   \
            *reinterpret_cast<float2*>(Bs + ((ks * 16 + nt) * 32 + ln) * 2) =         \
                make_float2(to_tf32f(rB[it].x), to_tf32f(rB[it].y));                  \
        }                                                                             \
    }

#define G2_MMA(s)                                                                     \
    {                                                                                 \
        const float* As = sm + (s) * 4096;                                            \
        const float* Bs = As + 2048;                                                  \
        _Pragma("unroll")                                                             \
        for (int ks = 0; ks < 2; ++ks) {                                              \
            uint4 af[4];                                                              \
            _Pragma("unroll")                                                         \
            for (int mt = 0; mt < 4; ++mt)                                            \
                af[mt] = *reinterpret_cast<const uint4*>(                             \
                    As + ((ks * 8 + wm * 4 + mt) * 32 + lane) * 4);                   \
            uint2 bf[4];                                                              \
            _Pragma("unroll")                                                         \
            for (int nt = 0; nt < 4; ++nt)                                            \
                bf[nt] = *reinterpret_cast<const uint2*>(                             \
                    Bs + ((ks * 16 + wn * 4 + nt) * 32 + lane) * 2);                  \
            _Pragma("unroll")                                                         \
            for (int mt = 0; mt < 4; ++mt)                                            \
                _Pragma("unroll")                                                     \
                for (int nt = 0; nt < 4; ++nt)                                        \
                    mma_tf32(acc[mt][nt], (const uint32_t*)&af[mt], (const uint32_t*)&bf[nt]); \
        }                                                                             \
    }

    G2_LOAD(0);
    G2_STORE(0);
    __syncthreads();

    const int NC = I_DIM / 16;
    for (int c = 0; c < NC; ++c) {
        if (c + 1 < NC) G2_LOAD((c + 1) * 16);
        G2_MMA(c & 1);
        __syncthreads();
        if (c + 1 < NC) {
            G2_STORE((c + 1) & 1);
            __syncthreads();
        }
    }

    // ---- epilogue: scale by combine weight, write slot buffer ----
#pragma unroll
    for (int mt = 0; mt < 4; ++mt) {
        int row_base = wm * 64 + mt * 16 + (lane >> 2);
#pragma unroll
        for (int h = 0; h < 2; ++h) {
            int gpos = m0 + row_base + h * 8;
            if (gpos >= count) continue;
            float w = g_wt[e][gpos];
            float* dst = g_y + ((size_t)e * T_TOK + gpos) * H_DIM + n0;
#pragma unroll
            for (int nt = 0; nt < 4; ++nt) {
                int col = wn * 32 + nt * 8 + (lane & 3) * 2;
                float2 o;
                o.x = w * acc[mt][nt][2 * h];
                o.y = w * acc[mt][nt][2 * h + 1];
                *reinterpret_cast<float2*>(dst + col) = o;
            }
        }
    }
#undef G2_LOAD
#undef G2_STORE
#undef G2_MMA
}

// ---------------- combine: out[t] = y[slot0] + y[slot1] ----------------
__global__ __launch_bounds__(256) void combine_kernel(float* __restrict__ out) {
    int t = blockIdx.x;
    int s0 = g_slot[t][0], s1 = g_slot[t][1];
    const float4* y0 = reinterpret_cast<const float4*>(g_y + (size_t)s0 * H_DIM);
    const float4* y1 = reinterpret_cast<const float4*>(g_y + (size_t)s1 * H_DIM);
    float4* o = reinterpret_cast<float4*>(out + (size_t)t * H_DIM);
    int c = threadIdx.x;
    float4 a = y0[c], b = y1[c];
    o[c] = make_float4(a.x + b.x, a.y + b.y, a.z + b.z, a.w + b.w);
}

// ---------------- launch ----------------
extern "C" void kernel_launch(void* const* d_in, const int* in_sizes, int n_in,
                              void* d_out, int out_size) {
    const float* hs = (const float*)d_in[0];   // [T, H]
    const float* gw = (const float*)d_in[1];   // [H, E]
    const float* wg = (const float*)d_in[2];   // [E, H, I]
    const float* wu = (const float*)d_in[3];   // [E, H, I]
    const float* wd = (const float*)d_in[4];   // [E, I, H]
    float* out = (float*)d_out;                // [T, H]

    zero_counts_kernel<<<1, 32>>>();
    router_kernel<<<T_TOK, 128>>>(hs, gw);

    dim3 g1(I_DIM / 64, T_TOK / 128, E_NUM);    // (32, 16, 8)
    gemm1_kernel<<<g1, 256>>>(hs, wg, wu);

    dim3 g2(H_DIM / 128, T_TOK / 128, E_NUM);   // (8, 16, 8)
    gemm2_kernel<<<g2, 256>>>(wd);

    combine_kernel<<<T_TOK, 256>>>(out);
}

// round 7
// speedup vs baseline: 2.4594x; 1.2662x over previous
#include <cuda_runtime.h>
#include <math.h>
#include <stdint.h>

#define T_TOK 2048
#define H_DIM 1024
#define E_NUM 8
#define I_DIM 2048

// ---------------- device scratch ----------------
__device__ int   g_count[E_NUM];
__device__ int   g_tok[E_NUM][T_TOK];
__device__ float g_wt[E_NUM][T_TOK];
__device__ int   g_slot[T_TOK][2];
__device__ float g_act[(size_t)E_NUM * T_TOK * I_DIM];   // 128 MB (tf32-rounded values)
__device__ float g_y[(size_t)E_NUM * T_TOK * H_DIM];     // 64 MB

// ---------------- helpers ----------------
__device__ __forceinline__ uint32_t to_tf32(float x) {
    uint32_t r; asm("cvt.rna.tf32.f32 %0, %1;" : "=r"(r) : "f"(x)); return r;
}
__device__ __forceinline__ float to_tf32f(float x) {
    return __uint_as_float(to_tf32(x));
}
__device__ __forceinline__ void mma_tf32(float* c, const uint32_t* a, const uint32_t* b) {
    asm volatile(
        "mma.sync.aligned.m16n8k8.row.col.f32.tf32.tf32.f32 "
        "{%0,%1,%2,%3}, {%4,%5,%6,%7}, {%8,%9}, {%0,%1,%2,%3};"
        : "+f"(c[0]), "+f"(c[1]), "+f"(c[2]), "+f"(c[3])
        : "r"(a[0]), "r"(a[1]), "r"(a[2]), "r"(a[3]), "r"(b[0]), "r"(b[1]));
}
// A-stage swizzle: physical unit = logical unit XOR ((ks<<1) ^ (bits[3:4] of unit))
__device__ __forceinline__ int aswz(int u, int ks) {
    return u ^ ((ks << 1) ^ ((u >> 3) & 3));
}

// ---------------- small kernels ----------------
__global__ void zero_counts_kernel() {
    if (threadIdx.x < E_NUM) g_count[threadIdx.x] = 0;
}

__global__ void router_kernel(const float* __restrict__ hs, const float* __restrict__ gw) {
    int t = blockIdx.x;
    const float* x = hs + (size_t)t * H_DIM;
    float acc[E_NUM];
#pragma unroll
    for (int e = 0; e < E_NUM; e++) acc[e] = 0.f;
    for (int j = threadIdx.x; j < H_DIM; j += blockDim.x) {
        float xv = x[j];
        const float4* grow = reinterpret_cast<const float4*>(gw + (size_t)j * E_NUM);
        float4 g0 = grow[0], g1 = grow[1];
        acc[0] += xv * g0.x; acc[1] += xv * g0.y; acc[2] += xv * g0.z; acc[3] += xv * g0.w;
        acc[4] += xv * g1.x; acc[5] += xv * g1.y; acc[6] += xv * g1.z; acc[7] += xv * g1.w;
    }
#pragma unroll
    for (int off = 16; off > 0; off >>= 1)
#pragma unroll
        for (int e = 0; e < E_NUM; e++)
            acc[e] += __shfl_xor_sync(0xffffffffu, acc[e], off);
    __shared__ float s[4][E_NUM];
    int warp = threadIdx.x >> 5, lane = threadIdx.x & 31;
    if (lane == 0)
#pragma unroll
        for (int e = 0; e < E_NUM; e++) s[warp][e] = acc[e];
    __syncthreads();
    if (threadIdx.x == 0) {
        float l[E_NUM];
#pragma unroll
        for (int e = 0; e < E_NUM; e++)
            l[e] = tanhf((s[0][e] + s[1][e] + s[2][e] + s[3][e]) * (1.0f / 30.0f));
        int i0 = 0;
#pragma unroll
        for (int e = 1; e < E_NUM; e++) if (l[e] > l[i0]) i0 = e;
        int i1 = (i0 == 0) ? 1 : 0;
#pragma unroll
        for (int e = 0; e < E_NUM; e++) if (e != i0 && l[e] > l[i1]) i1 = e;
        float d  = l[i1] - l[i0];
        float ed = expf(d);
        float inv = 1.0f / (1.0f + ed);
        float p0 = inv, p1 = ed * inv;
        int p = atomicAdd(&g_count[i0], 1);
        g_tok[i0][p] = t; g_wt[i0][p] = p0; g_slot[t][0] = i0 * T_TOK + p;
        p = atomicAdd(&g_count[i1], 1);
        g_tok[i1][p] = t; g_wt[i1][p] = p1; g_slot[t][1] = i1 * T_TOK + p;
    }
}

__device__ __forceinline__ float gelu_tanh(float g) {
    float c = 0.7978845608028654f * (g + 0.044715f * g * g * g);
    return 0.5f * g * (1.0f + tanhf(c));
}

// ============================================================================
// GEMM1: act = tf32( gelu(X@wg) * (X@wu) )   [per expert, gathered rows]
// CTA tile: M=128 x N=64 (both g and u). K=1024, kb=16, double-buffered,
// 2 CTAs/SM. Stage = A 2048 + Bg 1024 + Bu 1024 = 4096 floats (16KB).
// A-stage uses the XOR swizzle (store 2-way instead of 4-way conflicted).
// ============================================================================
__global__ __launch_bounds__(256, 2)
void gemm1_kernel(const float* __restrict__ hs,
                  const float* __restrict__ wg,
                  const float* __restrict__ wu) {
    const int e = blockIdx.z;
    const int count = g_count[e];
    const int m0 = blockIdx.y * 128;
    if (m0 >= count) return;
    const int n0 = blockIdx.x * 64;

    __shared__ float sm[2 * 4096];
    __shared__ int rowtok[128];

    const int tid = threadIdx.x, wid = tid >> 5, lane = tid & 31;
    const int wm = wid & 1, wn = wid >> 1;

    if (tid < 128) {
        int gp = m0 + tid;
        rowtok[tid] = (gp < count) ? g_tok[e][gp] : -1;
    }
    __syncthreads();

    const float* wgp = wg + (size_t)e * H_DIM * I_DIM + n0;
    const float* wup = wu + (size_t)e * H_DIM * I_DIM + n0;

    float accg[4][2][4], accu[4][2][4];
#pragma unroll
    for (int i = 0; i < 4; i++)
#pragma unroll
        for (int j = 0; j < 2; j++)
#pragma unroll
            for (int q = 0; q < 4; q++) { accg[i][j][q] = 0.f; accu[i][j][q] = 0.f; }

    float4 rA[2];
    float2 rBg[2], rBu[2];

#define G1_LOAD(k0)                                                                   \
    {                                                                                 \
        _Pragma("unroll")                                                             \
        for (int it = 0; it < 2; ++it) {                                              \
            int f = tid + it * 256;                                                   \
            int m = f >> 2, kq = (f & 3) << 2;                                        \
            int tok = rowtok[m];                                                      \
            rA[it] = (tok >= 0)                                                       \
                ? *reinterpret_cast<const float4*>(hs + (size_t)tok * H_DIM + (k0) + kq) \
                : make_float4(0.f, 0.f, 0.f, 0.f);                                    \
        }                                                                             \
        _Pragma("unroll")                                                             \
        for (int it = 0; it < 2; ++it) {                                              \
            int f = tid + it * 256;                                                   \
            int ln = f & 31, nt = (f >> 5) & 7, ks = (f >> 8) & 1;                    \
            int n = nt * 8 + (ln >> 2);                                               \
            int k = ks * 8 + (ln & 3);                                                \
            const float* pg = wgp + (size_t)((k0) + k) * I_DIM + n;                   \
            const float* pu = wup + (size_t)((k0) + k) * I_DIM + n;                   \
            rBg[it].x = pg[0];           rBg[it].y = pg[4 * I_DIM];                   \
            rBu[it].x = pu[0];           rBu[it].y = pu[4 * I_DIM];                   \
        }                                                                             \
    }

#define G1_STORE(s)                                                                   \
    {                                                                                 \
        float* As = sm + (s) * 4096;                                                  \
        float* Bgs = As + 2048;                                                       \
        float* Bus = As + 3072;                                                       \
        _Pragma("unroll")                                                             \
        for (int it = 0; it < 2; ++it) {                                              \
            int f = tid + it * 256;                                                   \
            int m = f >> 2, kq = (f & 3) << 2;                                        \
            int ks = kq >> 3, chalf = (kq >> 2) & 1;                                  \
            int reg = ((m >> 3) & 1) + 2 * chalf;                                     \
            int mt = m >> 4, lane0 = (m & 7) << 2;                                    \
            int slotb = (ks * 8 + mt) * 32;                                           \
            float v[4] = {rA[it].x, rA[it].y, rA[it].z, rA[it].w};                    \
            _Pragma("unroll")                                                         \
            for (int j = 0; j < 4; ++j)                                               \
                As[(slotb + aswz(lane0 + j, ks)) * 4 + reg] = to_tf32f(v[j]);         \
        }                                                                             \
        _Pragma("unroll")                                                             \
        for (int it = 0; it < 2; ++it) {                                              \
            int f = tid + it * 256;                                                   \
            int ln = f & 31, nt = (f >> 5) & 7, ks = (f >> 8) & 1;                    \
            int idx = ((ks * 8 + nt) * 32 + ln) * 2;                                  \
            *reinterpret_cast<float2*>(Bgs + idx) =                                   \
                make_float2(to_tf32f(rBg[it].x), to_tf32f(rBg[it].y));                \
            *reinterpret_cast<float2*>(Bus + idx) =                                   \
                make_float2(to_tf32f(rBu[it].x), to_tf32f(rBu[it].y));                \
        }                                                                             \
    }

#define G1_MMA(s)                                                                     \
    {                                                                                 \
        const float* As = sm + (s) * 4096;                                            \
        const float* Bgs = As + 2048;                                                 \
        const float* Bus = As + 3072;                                                 \
        _Pragma("unroll")                                                             \
        for (int ks = 0; ks < 2; ++ks) {                                              \
            int lsw = aswz(lane, ks);                                                 \
            uint4 af[4];                                                              \
            _Pragma("unroll")                                                         \
            for (int mt = 0; mt < 4; ++mt)                                            \
                af[mt] = *reinterpret_cast<const uint4*>(                             \
                    As + ((ks * 8 + wm * 4 + mt) * 32 + lsw) * 4);                    \
            uint2 bgf[2], buf_[2];                                                    \
            _Pragma("unroll")                                                         \
            for (int nt = 0; nt < 2; ++nt) {                                          \
                bgf[nt] = *reinterpret_cast<const uint2*>(                            \
                    Bgs + ((ks * 8 + wn * 2 + nt) * 32 + lane) * 2);                  \
                buf_[nt] = *reinterpret_cast<const uint2*>(                           \
                    Bus + ((ks * 8 + wn * 2 + nt) * 32 + lane) * 2);                  \
            }                                                                         \
            _Pragma("unroll")                                                         \
            for (int mt = 0; mt < 4; ++mt)                                            \
                _Pragma("unroll")                                                     \
                for (int nt = 0; nt < 2; ++nt) {                                      \
                    mma_tf32(accg[mt][nt], (const uint32_t*)&af[mt], (const uint32_t*)&bgf[nt]); \
                    mma_tf32(accu[mt][nt], (const uint32_t*)&af[mt], (const uint32_t*)&buf_[nt]); \
                }                                                                     \
        }                                                                             \
    }

    G1_LOAD(0);
    G1_STORE(0);
    __syncthreads();

    const int NC = H_DIM / 16;
    for (int c = 0; c < NC; ++c) {
        if (c + 1 < NC) G1_LOAD((c + 1) * 16);
        G1_MMA(c & 1);
        __syncthreads();
        if (c + 1 < NC) {
            G1_STORE((c + 1) & 1);
            __syncthreads();
        }
    }

    // ---- epilogue: fused gelu(g)*u, pre-rounded to tf32 for GEMM2 ----
#pragma unroll
    for (int mt = 0; mt < 4; ++mt) {
        int row_base = wm * 64 + mt * 16 + (lane >> 2);
#pragma unroll
        for (int nt = 0; nt < 2; ++nt) {
            int col = wn * 16 + nt * 8 + (lane & 3) * 2;
#pragma unroll
            for (int h = 0; h < 2; ++h) {
                int gpos = m0 + row_base + h * 8;
                if (gpos < count) {
                    float gv0 = accg[mt][nt][2 * h], gv1 = accg[mt][nt][2 * h + 1];
                    float uv0 = accu[mt][nt][2 * h], uv1 = accu[mt][nt][2 * h + 1];
                    float2 o;
                    o.x = to_tf32f(gelu_tanh(gv0) * uv0);
                    o.y = to_tf32f(gelu_tanh(gv1) * uv1);
                    *reinterpret_cast<float2*>(
                        g_act + ((size_t)e * T_TOK + gpos) * I_DIM + n0 + col) = o;
                }
            }
        }
    }
#undef G1_LOAD
#undef G1_STORE
#undef G1_MMA
}

// ============================================================================
// GEMM2: y = weight * (act @ wd)   [per expert]
// CTA tile: M=128 x N=256, warp tile 64x64 (1.0 LDS-wf/mma). K=2048, kb=16,
// double-buffered. Stage = A 2048 + B 4096 = 6144 floats (24KB); 48KB total.
// ============================================================================
__global__ __launch_bounds__(256, 1)
void gemm2_kernel(const float* __restrict__ wd) {
    const int e = blockIdx.z;
    const int count = g_count[e];
    const int m0 = blockIdx.y * 128;
    if (m0 >= count) return;
    const int n0 = blockIdx.x * 256;

    __shared__ float sm[2 * 6144];

    const int tid = threadIdx.x, wid = tid >> 5, lane = tid & 31;
    const int wm = wid & 1, wn = wid >> 1;   // wn in [0,4): 64-col slab

    const float* actp = g_act + (size_t)e * T_TOK * I_DIM;
    const float* wdp  = wd + (size_t)e * I_DIM * H_DIM + n0;

    float acc[4][8][4];
#pragma unroll
    for (int i = 0; i < 4; i++)
#pragma unroll
        for (int j = 0; j < 8; j++)
#pragma unroll
            for (int q = 0; q < 4; q++) acc[i][j][q] = 0.f;

    float4 rA[2];
    float2 rB[8];

#define G2_LOAD(k0)                                                                   \
    {                                                                                 \
        _Pragma("unroll")                                                             \
        for (int it = 0; it < 2; ++it) {                                              \
            int f = tid + it * 256;                                                   \
            int m = f >> 2, kq = (f & 3) << 2;                                        \
            int gp = m0 + m;                                                          \
            rA[it] = (gp < count)                                                     \
                ? *reinterpret_cast<const float4*>(actp + (size_t)gp * I_DIM + (k0) + kq) \
                : make_float4(0.f, 0.f, 0.f, 0.f);                                    \
        }                                                                             \
        _Pragma("unroll")                                                             \
        for (int it = 0; it < 8; ++it) {                                              \
            int f = tid + it * 256;                                                   \
            int ln = f & 31, nt = (f >> 5) & 31, ks = (f >> 10) & 1;                  \
            int n = nt * 8 + (ln >> 2);                                               \
            int k = ks * 8 + (ln & 3);                                                \
            const float* pb = wdp + (size_t)((k0) + k) * H_DIM + n;                   \
            rB[it].x = pb[0];            rB[it].y = pb[4 * H_DIM];                    \
        }                                                                             \
    }

#define G2_STORE(s)                                                                   \
    {                                                                                 \
        float* As = sm + (s) * 6144;                                                  \
        float* Bs = As + 2048;                                                        \
        _Pragma("unroll")                                                             \
        for (int it = 0; it < 2; ++it) {                                              \
            int f = tid + it * 256;                                                   \
            int m = f >> 2, kq = (f & 3) << 2;                                        \
            int ks = kq >> 3, chalf = (kq >> 2) & 1;                                  \
            int reg = ((m >> 3) & 1) + 2 * chalf;                                     \
            int mt = m >> 4, lane0 = (m & 7) << 2;                                    \
            int slotb = (ks * 8 + mt) * 32;                                           \
            float v[4] = {rA[it].x, rA[it].y, rA[it].z, rA[it].w};                    \
            _Pragma("unroll")                                                         \
            for (int j = 0; j < 4; ++j)                                               \
                As[(slotb + aswz(lane0 + j, ks)) * 4 + reg] = v[j];                   \
        }                                                                             \
        _Pragma("unroll")                                                             \
        for (int it = 0; it < 8; ++it) {                                              \
            int f = tid + it * 256;                                                   \
            int ln = f & 31, nt = (f >> 5) & 31, ks = (f >> 10) & 1;                  \
            *reinterpret_cast<float2*>(Bs + ((ks * 32 + nt) * 32 + ln) * 2) =         \
                make_float2(to_tf32f(rB[it].x), to_tf32f(rB[it].y));                  \
        }                                                                             \
    }

#define G2_MMA(s)                                                                     \
    {                                                                                 \
        const float* As = sm + (s) * 6144;                                            \
        const float* Bs = As + 2048;                                                  \
        _Pragma("unroll")                                                             \
        for (int ks = 0; ks < 2; ++ks) {                                              \
            int lsw = aswz(lane, ks);                                                 \
            uint4 af[4];                                                              \
            _Pragma("unroll")                                                         \
            for (int mt = 0; mt < 4; ++mt)                                            \
                af[mt] = *reinterpret_cast<const uint4*>(                             \
                    As + ((ks * 8 + wm * 4 + mt) * 32 + lsw) * 4);                    \
            uint2 bf[8];                                                              \
            _Pragma("unroll")                                                         \
            for (int nt = 0; nt < 8; ++nt)                                            \
                bf[nt] = *reinterpret_cast<const uint2*>(                             \
                    Bs + ((ks * 32 + wn * 8 + nt) * 32 + lane) * 2);                  \
            _Pragma("unroll")                                                         \
            for (int mt = 0; mt < 4; ++mt)                                            \
                _Pragma("unroll")                                                     \
                for (int nt = 0; nt < 8; ++nt)                                        \
                    mma_tf32(acc[mt][nt], (const uint32_t*)&af[mt], (const uint32_t*)&bf[nt]); \
        }                                                                             \
    }

    G2_LOAD(0);
    G2_STORE(0);
    __syncthreads();

    const int NC = I_DIM / 16;
    for (int c = 0; c < NC; ++c) {
        if (c + 1 < NC) G2_LOAD((c + 1) * 16);
        G2_MMA(c & 1);
        __syncthreads();
        if (c + 1 < NC) {
            G2_STORE((c + 1) & 1);
            __syncthreads();
        }
    }

    // ---- epilogue: scale by combine weight, write slot buffer ----
#pragma unroll
    for (int mt = 0; mt < 4; ++mt) {
        int row_base = wm * 64 + mt * 16 + (lane >> 2);
#pragma unroll
        for (int h = 0; h < 2; ++h) {
            int gpos = m0 + row_base + h * 8;
            if (gpos >= count) continue;
            float w = g_wt[e][gpos];
            float* dst = g_y + ((size_t)e * T_TOK + gpos) * H_DIM + n0;
#pragma unroll
            for (int nt = 0; nt < 8; ++nt) {
                int col = wn * 64 + nt * 8 + (lane & 3) * 2;
                float2 o;
                o.x = w * acc[mt][nt][2 * h];
                o.y = w * acc[mt][nt][2 * h + 1];
                *reinterpret_cast<float2*>(dst + col) = o;
            }
        }
    }
#undef G2_LOAD
#undef G2_STORE
#undef G2_MMA
}

// ---------------- combine: out[t] = y[slot0] + y[slot1] ----------------
__global__ __launch_bounds__(256) void combine_kernel(float* __restrict__ out) {
    int t = blockIdx.x;
    int s0 = g_slot[t][0], s1 = g_slot[t][1];
    const float4* y0 = reinterpret_cast<const float4*>(g_y + (size_t)s0 * H_DIM);
    const float4* y1 = reinterpret_cast<const float4*>(g_y + (size_t)s1 * H_DIM);
    float4* o = reinterpret_cast<float4*>(out + (size_t)t * H_DIM);
    int c = threadIdx.x;
    float4 a = y0[c], b = y1[c];
    o[c] = make_float4(a.x + b.x, a.y + b.y, a.z + b.z, a.w + b.w);
}

// ---------------- launch ----------------
extern "C" void kernel_launch(void* const* d_in, const int* in_sizes, int n_in,
                              void* d_out, int out_size) {
    const float* hs = (const float*)d_in[0];   // [T, H]
    const float* gw = (const float*)d_in[1];   // [H, E]
    const float* wg = (const float*)d_in[2];   // [E, H, I]
    const float* wu = (const float*)d_in[3];   // [E, H, I]
    const float* wd = (const float*)d_in[4];   // [E, I, H]
    float* out = (float*)d_out;                // [T, H]

    zero_counts_kernel<<<1, 32>>>();
    router_kernel<<<T_TOK, 128>>>(hs, gw);

    dim3 g1(I_DIM / 64, T_TOK / 128, E_NUM);    // (32, 16, 8)
    gemm1_kernel<<<g1, 256>>>(hs, wg, wu);

    dim3 g2(H_DIM / 256, T_TOK / 128, E_NUM);   // (4, 16, 8)
    gemm2_kernel<<<g2, 256>>>(wd);

    combine_kernel<<<T_TOK, 256>>>(out);
}